// round 7
// baseline (speedup 1.0000x reference)
#include <cuda_runtime.h>
#include <cuda_bf16.h>
#include <math.h>
#include <stdint.h>

#define N_NODES 100000
#define E_EDGES 1600000
#define C_DIM 256
#define H_DIM 128
#define F_DIM 64

// Scratch (__device__ globals; no allocation allowed)
__device__ float g_buf1[N_NODES * H_DIM];
__device__ float g_buf2[N_NODES * H_DIM];
__device__ int   g_rowptr[N_NODES + 1];

// ---------------------------------------------------------------------------
// Helpers
// ---------------------------------------------------------------------------
__device__ __forceinline__ uint32_t smem_u32(const void* p) {
    uint32_t a;
    asm("{ .reg .u64 t; cvta.to.shared.u64 t, %1; cvt.u32.u64 %0, t; }" : "=r"(a) : "l"(p));
    return a;
}
__device__ __forceinline__ uint32_t f2tf32(float f) {
    uint32_t o;
    asm("cvt.rna.tf32.f32 %0, %1;" : "=r"(o) : "f"(f));
    return o;
}
__device__ __forceinline__ void mma_tf32(float (&d)[4], const uint32_t (&a)[4],
                                         uint32_t b0, uint32_t b1) {
    asm volatile(
        "mma.sync.aligned.m16n8k8.row.col.f32.tf32.tf32.f32 "
        "{%0,%1,%2,%3}, {%4,%5,%6,%7}, {%8,%9}, {%0,%1,%2,%3};"
        : "+f"(d[0]), "+f"(d[1]), "+f"(d[2]), "+f"(d[3])
        : "r"(a[0]), "r"(a[1]), "r"(a[2]), "r"(a[3]), "r"(b0), "r"(b1));
}
__device__ __forceinline__ void cp_async16(uint32_t dst, const void* src, int srcsize) {
    asm volatile("cp.async.cg.shared.global [%0], [%1], 16, %2;"
                 :: "r"(dst), "l"(src), "r"(srcsize));
}
#define CP_COMMIT() asm volatile("cp.async.commit_group;" ::: "memory")
template<int NW> __device__ __forceinline__ void cp_wait() {
    asm volatile("cp.async.wait_group %0;" :: "n"(NW) : "memory");
}

// ---------------------------------------------------------------------------
// Row-pointer build: lower_bound over sorted edge_row
// ---------------------------------------------------------------------------
__global__ void rowptr_kernel(const int* __restrict__ edge_row) {
    int i = blockIdx.x * blockDim.x + threadIdx.x;
    if (i > N_NODES) return;
    int lo = 0, hi = E_EDGES;
    while (lo < hi) {
        int mid = (lo + hi) >> 1;
        if (edge_row[mid] < i) lo = mid + 1;
        else hi = mid;
    }
    g_rowptr[i] = lo;
}

// ---------------------------------------------------------------------------
// tf32 tensor-core GEMM, 3-stage cp.async pipeline, ONE barrier per chunk:
//   out[m][n] = sum_k A[m][k] * W[n][k]
// BM=128, BK=32, 256 threads (8 warps), 2 CTAs/SM.
// Smem rows: 36 floats (144B) stride, conflict-free for fragment LDS.
// Safety: fill((kc+2)%3) issued after compute(kc); barrier at top of kc
// guarantees every warp finished compute(kc-1) (the stage being refilled).
// ---------------------------------------------------------------------------
template<int N, int K>
__global__ void __launch_bounds__(256, 2) gemm_tf32p(const float* __restrict__ A,
                                                     const float* __restrict__ W,
                                                     float* __restrict__ out, int M) {
    constexpr int BM = 128;
    constexpr int LDSW = 36;                        // floats per smem row
    constexpr int AFLOATS = BM * LDSW;
    constexpr int WFLOATS = N * LDSW;
    constexpr int STAGEF  = AFLOATS + WFLOATS;
    constexpr int NC = K / 32;
    constexpr int WCOLS = N / 32;
    constexpr int WROWS = 8 / WCOLS;
    constexpr int WTM = BM / WROWS;                 // 64 or 32
    constexpr int MT = WTM / 16;                    // 4 or 2

    extern __shared__ float smem[];
    const uint32_t sb = smem_u32(smem);

    const int tid  = threadIdx.x;
    const int wid  = tid >> 5;
    const int lane = tid & 31;
    const int wm   = (wid / WCOLS) * WTM;
    const int wn   = (wid % WCOLS) * 32;
    const int bm   = blockIdx.x * BM;
    const int arows = min(BM, M - bm);

    const int fr = lane >> 2;
    const int fc = lane & 3;

    float acc[MT][4][4];
#pragma unroll
    for (int i = 0; i < MT; i++)
#pragma unroll
        for (int j = 0; j < 4; j++)
#pragma unroll
            for (int c = 0; c < 4; c++) acc[i][j][c] = 0.f;

    auto fill = [&](int s, int k0) {
        const uint32_t base = sb + (uint32_t)(s * STAGEF * 4);
#pragma unroll
        for (int idx = tid; idx < BM * 8; idx += 256) {
            int row = idx >> 3, g = idx & 7;
            int sz = (row < arows) ? 16 : 0;
            cp_async16(base + (uint32_t)(row * 144 + g * 16),
                       &A[(size_t)(bm + row) * K + k0 + g * 4], sz);
        }
#pragma unroll
        for (int idx = tid; idx < N * 8; idx += 256) {
            int row = idx >> 3, g = idx & 7;
            cp_async16(base + (uint32_t)(AFLOATS * 4 + row * 144 + g * 16),
                       &W[(size_t)row * K + k0 + g * 4], 16);
        }
        CP_COMMIT();
    };

    fill(0, 0);
    if (NC > 1) fill(1, 32);

    for (int kc = 0; kc < NC; kc++) {
        if (kc + 1 < NC) cp_wait<1>(); else cp_wait<0>();
        __syncthreads();

        const float* sA = smem + (kc % 3) * STAGEF;
        const float* sW = sA + AFLOATS;

#pragma unroll
        for (int ks = 0; ks < 4; ks++) {
            const int kb = ks * 8 + fc;
            uint32_t af[MT][4];
#pragma unroll
            for (int mt = 0; mt < MT; mt++) {
                int base = (wm + mt * 16 + fr) * LDSW + kb;
                af[mt][0] = f2tf32(sA[base]);
                af[mt][1] = f2tf32(sA[base + 8 * LDSW]);
                af[mt][2] = f2tf32(sA[base + 4]);
                af[mt][3] = f2tf32(sA[base + 8 * LDSW + 4]);
            }
            uint32_t bf[4][2];
#pragma unroll
            for (int nt = 0; nt < 4; nt++) {
                int base = (wn + nt * 8 + fr) * LDSW + kb;
                bf[nt][0] = f2tf32(sW[base]);
                bf[nt][1] = f2tf32(sW[base + 4]);
            }
#pragma unroll
            for (int mt = 0; mt < MT; mt++)
#pragma unroll
                for (int nt = 0; nt < 4; nt++)
                    mma_tf32(acc[mt][nt], af[mt], bf[nt][0], bf[nt][1]);
        }

        if (kc + 2 < NC) fill((kc + 2) % 3, (kc + 2) * 32);
    }

    // Epilogue
#pragma unroll
    for (int mt = 0; mt < MT; mt++) {
#pragma unroll
        for (int nt = 0; nt < 4; nt++) {
            int r0 = wm + mt * 16 + fr;
            int c0 = wn + nt * 8 + fc * 2;
            if (r0 < arows)
                *reinterpret_cast<float2*>(&out[(size_t)(bm + r0) * N + c0]) =
                    make_float2(acc[mt][nt][0], acc[mt][nt][1]);
            if (r0 + 8 < arows)
                *reinterpret_cast<float2*>(&out[(size_t)(bm + r0 + 8) * N + c0]) =
                    make_float2(acc[mt][nt][2], acc[mt][nt][3]);
        }
    }
}

// ---------------------------------------------------------------------------
// SpMM (H=128): one warp per row, float4 per lane, ReLU, 4x edge unroll (MLP)
// ---------------------------------------------------------------------------
template<bool RELU>
__global__ void __launch_bounds__(256) spmm128_kernel(const int* __restrict__ edge_col,
                                                      const float* __restrict__ edge_val,
                                                      const float* __restrict__ Z,
                                                      float* __restrict__ out) {
    int gw   = (blockIdx.x * blockDim.x + threadIdx.x) >> 5;
    int lane = threadIdx.x & 31;
    if (gw >= N_NODES) return;
    int s = g_rowptr[gw];
    int e = g_rowptr[gw + 1];

    float4 acc = make_float4(0.f, 0.f, 0.f, 0.f);
    int i = s;
    for (; i + 4 <= e; i += 4) {
        int   c0 = __ldg(&edge_col[i + 0]);
        int   c1 = __ldg(&edge_col[i + 1]);
        int   c2 = __ldg(&edge_col[i + 2]);
        int   c3 = __ldg(&edge_col[i + 3]);
        float v0 = __ldg(&edge_val[i + 0]);
        float v1 = __ldg(&edge_val[i + 1]);
        float v2 = __ldg(&edge_val[i + 2]);
        float v3 = __ldg(&edge_val[i + 3]);
        float4 z0 = *reinterpret_cast<const float4*>(&Z[(size_t)c0 * H_DIM + lane * 4]);
        float4 z1 = *reinterpret_cast<const float4*>(&Z[(size_t)c1 * H_DIM + lane * 4]);
        float4 z2 = *reinterpret_cast<const float4*>(&Z[(size_t)c2 * H_DIM + lane * 4]);
        float4 z3 = *reinterpret_cast<const float4*>(&Z[(size_t)c3 * H_DIM + lane * 4]);
        acc.x = fmaf(v0, z0.x, acc.x); acc.y = fmaf(v0, z0.y, acc.y);
        acc.z = fmaf(v0, z0.z, acc.z); acc.w = fmaf(v0, z0.w, acc.w);
        acc.x = fmaf(v1, z1.x, acc.x); acc.y = fmaf(v1, z1.y, acc.y);
        acc.z = fmaf(v1, z1.z, acc.z); acc.w = fmaf(v1, z1.w, acc.w);
        acc.x = fmaf(v2, z2.x, acc.x); acc.y = fmaf(v2, z2.y, acc.y);
        acc.z = fmaf(v2, z2.z, acc.z); acc.w = fmaf(v2, z2.w, acc.w);
        acc.x = fmaf(v3, z3.x, acc.x); acc.y = fmaf(v3, z3.y, acc.y);
        acc.z = fmaf(v3, z3.z, acc.z); acc.w = fmaf(v3, z3.w, acc.w);
    }
    for (; i < e; i++) {
        int   col = __ldg(&edge_col[i]);
        float val = __ldg(&edge_val[i]);
        float4 z = *reinterpret_cast<const float4*>(&Z[(size_t)col * H_DIM + lane * 4]);
        acc.x = fmaf(val, z.x, acc.x);
        acc.y = fmaf(val, z.y, acc.y);
        acc.z = fmaf(val, z.z, acc.z);
        acc.w = fmaf(val, z.w, acc.w);
    }
    if (RELU) {
        acc.x = fmaxf(acc.x, 0.f);
        acc.y = fmaxf(acc.y, 0.f);
        acc.z = fmaxf(acc.z, 0.f);
        acc.w = fmaxf(acc.w, 0.f);
    }
    *reinterpret_cast<float4*>(&out[(size_t)gw * H_DIM + lane * 4]) = acc;
}

// ---------------------------------------------------------------------------
// Final SpMM (F=64) fused with row softmax, 4x edge unroll
// ---------------------------------------------------------------------------
__global__ void __launch_bounds__(256) spmm64_softmax_kernel(const int* __restrict__ edge_col,
                                                             const float* __restrict__ edge_val,
                                                             const float* __restrict__ Z,
                                                             float* __restrict__ out) {
    int gw   = (blockIdx.x * blockDim.x + threadIdx.x) >> 5;
    int lane = threadIdx.x & 31;
    if (gw >= N_NODES) return;
    int s = g_rowptr[gw];
    int e = g_rowptr[gw + 1];

    float a0 = 0.f, a1 = 0.f;
    int i = s;
    for (; i + 4 <= e; i += 4) {
        int   c0 = __ldg(&edge_col[i + 0]);
        int   c1 = __ldg(&edge_col[i + 1]);
        int   c2 = __ldg(&edge_col[i + 2]);
        int   c3 = __ldg(&edge_col[i + 3]);
        float v0 = __ldg(&edge_val[i + 0]);
        float v1 = __ldg(&edge_val[i + 1]);
        float v2 = __ldg(&edge_val[i + 2]);
        float v3 = __ldg(&edge_val[i + 3]);
        float2 z0 = *reinterpret_cast<const float2*>(&Z[(size_t)c0 * F_DIM + lane * 2]);
        float2 z1 = *reinterpret_cast<const float2*>(&Z[(size_t)c1 * F_DIM + lane * 2]);
        float2 z2 = *reinterpret_cast<const float2*>(&Z[(size_t)c2 * F_DIM + lane * 2]);
        float2 z3 = *reinterpret_cast<const float2*>(&Z[(size_t)c3 * F_DIM + lane * 2]);
        a0 = fmaf(v0, z0.x, a0); a1 = fmaf(v0, z0.y, a1);
        a0 = fmaf(v1, z1.x, a0); a1 = fmaf(v1, z1.y, a1);
        a0 = fmaf(v2, z2.x, a0); a1 = fmaf(v2, z2.y, a1);
        a0 = fmaf(v3, z3.x, a0); a1 = fmaf(v3, z3.y, a1);
    }
    for (; i < e; i++) {
        int   col = __ldg(&edge_col[i]);
        float val = __ldg(&edge_val[i]);
        float2 z = *reinterpret_cast<const float2*>(&Z[(size_t)col * F_DIM + lane * 2]);
        a0 = fmaf(val, z.x, a0);
        a1 = fmaf(val, z.y, a1);
    }
    float m = fmaxf(a0, a1);
#pragma unroll
    for (int off = 16; off > 0; off >>= 1)
        m = fmaxf(m, __shfl_xor_sync(0xFFFFFFFFu, m, off));
    float e0 = expf(a0 - m);
    float e1 = expf(a1 - m);
    float ssum = e0 + e1;
#pragma unroll
    for (int off = 16; off > 0; off >>= 1)
        ssum += __shfl_xor_sync(0xFFFFFFFFu, ssum, off);
    float inv = 1.0f / ssum;
    *reinterpret_cast<float2*>(&out[(size_t)gw * F_DIM + lane * 2]) =
        make_float2(e0 * inv, e1 * inv);
}

// ---------------------------------------------------------------------------
// Launch
// ---------------------------------------------------------------------------
extern "C" void kernel_launch(void* const* d_in, const int* in_sizes, int n_in,
                              void* d_out, int out_size) {
    const float* X        = (const float*)d_in[0];
    const int*   edge_row = (const int*)d_in[1];
    const int*   edge_col = (const int*)d_in[2];
    const float* edge_val = (const float*)d_in[3];
    const float* W0       = (const float*)d_in[4];
    const float* Wh0      = (const float*)d_in[5];
    const float* W1       = (const float*)d_in[6];
    float*       out      = (float*)d_out;

    float *buf1, *buf2;
    cudaGetSymbolAddress((void**)&buf1, g_buf1);
    cudaGetSymbolAddress((void**)&buf2, g_buf2);

    constexpr int SMEM_128 = 3 * (128 + 128) * 144;   // 110592
    constexpr int SMEM_64  = 3 * (128 + 64) * 144;    // 82944
    cudaFuncSetAttribute(gemm_tf32p<128, 256>, cudaFuncAttributeMaxDynamicSharedMemorySize, SMEM_128);
    cudaFuncSetAttribute(gemm_tf32p<128, 128>, cudaFuncAttributeMaxDynamicSharedMemorySize, SMEM_128);
    cudaFuncSetAttribute(gemm_tf32p<64, 128>,  cudaFuncAttributeMaxDynamicSharedMemorySize, SMEM_64);

    const int gemm_grid = (N_NODES + 127) / 128;       // 782
    const int spmm_grid = (N_NODES * 32 + 255) / 256;  // 12500

    rowptr_kernel<<<(N_NODES + 1 + 255) / 256, 256>>>(edge_row);

    // Layer 0: buf1 = X @ W0^T ; buf2 = relu(A @ buf1)
    gemm_tf32p<128, 256><<<gemm_grid, 256, SMEM_128>>>(X, W0, buf1, N_NODES);
    spmm128_kernel<true><<<spmm_grid, 256>>>(edge_col, edge_val, buf1, buf2);

    // Hidden: buf1 = buf2 @ Wh0^T ; buf2 = relu(A @ buf1)
    gemm_tf32p<128, 128><<<gemm_grid, 256, SMEM_128>>>(buf2, Wh0, buf1, N_NODES);
    spmm128_kernel<true><<<spmm_grid, 256>>>(edge_col, edge_val, buf1, buf2);

    // Output: buf1 = buf2 @ W1^T ; out = softmax(A @ buf1)
    gemm_tf32p<64, 128><<<gemm_grid, 256, SMEM_64>>>(buf2, W1, buf1, N_NODES);
    spmm64_softmax_kernel<<<spmm_grid, 256>>>(edge_col, edge_val, buf1, out);
}

// round 8
// speedup vs baseline: 1.0927x; 1.0927x over previous
#include <cuda_runtime.h>
#include <cuda_fp16.h>
#include <math.h>
#include <stdint.h>

#define N_NODES 100000
#define E_EDGES 1600000
#define C_DIM 256
#define H_DIM 128
#define F_DIM 64

// Scratch (__device__ globals; no allocation allowed)
__device__ __half g_hbuf1[N_NODES * H_DIM];   // GEMM outputs (pre-aggregation)
__device__ __half g_hbuf2[N_NODES * H_DIM];   // SpMM outputs (activations)
__device__ int    g_rowptr[N_NODES + 1];

// ---------------------------------------------------------------------------
// Helpers
// ---------------------------------------------------------------------------
__device__ __forceinline__ uint32_t smem_u32(const void* p) {
    uint32_t a;
    asm("{ .reg .u64 t; cvta.to.shared.u64 t, %1; cvt.u32.u64 %0, t; }" : "=r"(a) : "l"(p));
    return a;
}
__device__ __forceinline__ uint32_t f2tf32(float f) {
    uint32_t o;
    asm("cvt.rna.tf32.f32 %0, %1;" : "=r"(o) : "f"(f));
    return o;
}
__device__ __forceinline__ void mma_tf32(float (&d)[4], const uint32_t (&a)[4],
                                         uint32_t b0, uint32_t b1) {
    asm volatile(
        "mma.sync.aligned.m16n8k8.row.col.f32.tf32.tf32.f32 "
        "{%0,%1,%2,%3}, {%4,%5,%6,%7}, {%8,%9}, {%0,%1,%2,%3};"
        : "+f"(d[0]), "+f"(d[1]), "+f"(d[2]), "+f"(d[3])
        : "r"(a[0]), "r"(a[1]), "r"(a[2]), "r"(a[3]), "r"(b0), "r"(b1));
}
__device__ __forceinline__ void cp_async16(uint32_t dst, const void* src, int srcsize) {
    asm volatile("cp.async.cg.shared.global [%0], [%1], 16, %2;"
                 :: "r"(dst), "l"(src), "r"(srcsize));
}
#define CP_COMMIT() asm volatile("cp.async.commit_group;" ::: "memory")
template<int NW> __device__ __forceinline__ void cp_wait() {
    asm volatile("cp.async.wait_group %0;" :: "n"(NW) : "memory");
}

// ---------------------------------------------------------------------------
// Row-pointer build: lower_bound over sorted edge_row
// ---------------------------------------------------------------------------
__global__ void rowptr_kernel(const int* __restrict__ edge_row) {
    int i = blockIdx.x * blockDim.x + threadIdx.x;
    if (i > N_NODES) return;
    int lo = 0, hi = E_EDGES;
    while (lo < hi) {
        int mid = (lo + hi) >> 1;
        if (edge_row[mid] < i) lo = mid + 1;
        else hi = mid;
    }
    g_rowptr[i] = lo;
}

// ---------------------------------------------------------------------------
// tf32 tensor-core GEMM, 3-stage cp.async pipeline, one barrier per chunk.
//   out[m][n] = (half) sum_k A[m][k] * W[n][k]
// A: fp32 (layer 0) or fp16 (layers 1-2), W: fp32, out: fp16.
// BM=128, BK=32, 256 threads (8 warps), 2 CTAs/SM.
// A-smem rows: fp32 -> 36 floats (144B); fp16 -> 40 halves (80B, 16B-aligned,
//   word index 20*row+j -> conflict-free). W-smem rows: 36 floats.
// ---------------------------------------------------------------------------
template<int N, int K, typename TA>
__global__ void __launch_bounds__(256, 2) gemm_tf32p(const TA* __restrict__ A,
                                                     const float* __restrict__ W,
                                                     __half* __restrict__ out, int M) {
    constexpr bool AH = (sizeof(TA) == 2);
    constexpr int BM = 128;
    constexpr int LDSA = AH ? 40 : 36;          // elements per A smem row
    constexpr int ABYTES = BM * LDSA * sizeof(TA);
    constexpr int LDSW = 36;
    constexpr int WBYTES = N * LDSW * 4;
    constexpr int STAGEB = ABYTES + WBYTES;
    constexpr int NC = K / 32;
    constexpr int WCOLS = N / 32;
    constexpr int WROWS = 8 / WCOLS;
    constexpr int WTM = BM / WROWS;
    constexpr int MT = WTM / 16;
    constexpr int ACHUNKS = AH ? 4 : 8;         // 16B chunks per 32-elem A row

    extern __shared__ char smem[];
    const uint32_t sb = smem_u32(smem);

    const int tid  = threadIdx.x;
    const int wid  = tid >> 5;
    const int lane = tid & 31;
    const int wm   = (wid / WCOLS) * WTM;
    const int wn   = (wid % WCOLS) * 32;
    const int bm   = blockIdx.x * BM;
    const int arows = min(BM, M - bm);

    const int fr = lane >> 2;
    const int fc = lane & 3;

    float acc[MT][4][4];
#pragma unroll
    for (int i = 0; i < MT; i++)
#pragma unroll
        for (int j = 0; j < 4; j++)
#pragma unroll
            for (int c = 0; c < 4; c++) acc[i][j][c] = 0.f;

    auto fill = [&](int s, int k0) {
        const uint32_t base = sb + (uint32_t)(s * STAGEB);
#pragma unroll
        for (int idx = tid; idx < BM * ACHUNKS; idx += 256) {
            int row = idx / ACHUNKS, g = idx % ACHUNKS;
            int sz = (row < arows) ? 16 : 0;
            cp_async16(base + (uint32_t)(row * LDSA * sizeof(TA) + g * 16),
                       &A[(size_t)(bm + row) * K + k0 + g * (16 / sizeof(TA))], sz);
        }
#pragma unroll
        for (int idx = tid; idx < N * 8; idx += 256) {
            int row = idx >> 3, g = idx & 7;
            cp_async16(base + (uint32_t)(ABYTES + row * 144 + g * 16),
                       &W[(size_t)row * K + k0 + g * 4], 16);
        }
        CP_COMMIT();
    };

    fill(0, 0);
    if (NC > 1) fill(1, 32);

    for (int kc = 0; kc < NC; kc++) {
        if (kc + 1 < NC) cp_wait<1>(); else cp_wait<0>();
        __syncthreads();

        const char* stg = smem + (kc % 3) * STAGEB;
        const TA*    sA = reinterpret_cast<const TA*>(stg);
        const float* sW = reinterpret_cast<const float*>(stg + ABYTES);

#pragma unroll
        for (int ks = 0; ks < 4; ks++) {
            const int kb = ks * 8 + fc;
            uint32_t af[MT][4];
#pragma unroll
            for (int mt = 0; mt < MT; mt++) {
                int base = (wm + mt * 16 + fr) * LDSA + kb;
                if constexpr (AH) {
                    af[mt][0] = f2tf32(__half2float(sA[base]));
                    af[mt][1] = f2tf32(__half2float(sA[base + 8 * LDSA]));
                    af[mt][2] = f2tf32(__half2float(sA[base + 4]));
                    af[mt][3] = f2tf32(__half2float(sA[base + 8 * LDSA + 4]));
                } else {
                    af[mt][0] = f2tf32(sA[base]);
                    af[mt][1] = f2tf32(sA[base + 8 * LDSA]);
                    af[mt][2] = f2tf32(sA[base + 4]);
                    af[mt][3] = f2tf32(sA[base + 8 * LDSA + 4]);
                }
            }
            uint32_t bf[4][2];
#pragma unroll
            for (int nt = 0; nt < 4; nt++) {
                int base = (wn + nt * 8 + fr) * LDSW + kb;
                bf[nt][0] = f2tf32(sW[base]);
                bf[nt][1] = f2tf32(sW[base + 4]);
            }
#pragma unroll
            for (int mt = 0; mt < MT; mt++)
#pragma unroll
                for (int nt = 0; nt < 4; nt++)
                    mma_tf32(acc[mt][nt], af[mt], bf[nt][0], bf[nt][1]);
        }

        if (kc + 2 < NC) fill((kc + 2) % 3, (kc + 2) * 32);
    }

    // Epilogue: fp16 store
#pragma unroll
    for (int mt = 0; mt < MT; mt++) {
#pragma unroll
        for (int nt = 0; nt < 4; nt++) {
            int r0 = wm + mt * 16 + fr;
            int c0 = wn + nt * 8 + fc * 2;
            if (r0 < arows)
                *reinterpret_cast<__half2*>(&out[(size_t)(bm + r0) * N + c0]) =
                    __floats2half2_rn(acc[mt][nt][0], acc[mt][nt][1]);
            if (r0 + 8 < arows)
                *reinterpret_cast<__half2*>(&out[(size_t)(bm + r0 + 8) * N + c0]) =
                    __floats2half2_rn(acc[mt][nt][2], acc[mt][nt][3]);
        }
    }
}

// ---------------------------------------------------------------------------
// SpMM (H=128), fp16 gather / fp32 accumulate / ReLU / fp16 store.
// One warp per row, 4 halves (8B) per lane, 4x edge unroll.
// ---------------------------------------------------------------------------
__device__ __forceinline__ void fma_h4(float4& acc, float v, uint2 zz) {
    __half2 h0 = *reinterpret_cast<__half2*>(&zz.x);
    __half2 h1 = *reinterpret_cast<__half2*>(&zz.y);
    float2 f0 = __half22float2(h0);
    float2 f1 = __half22float2(h1);
    acc.x = fmaf(v, f0.x, acc.x);
    acc.y = fmaf(v, f0.y, acc.y);
    acc.z = fmaf(v, f1.x, acc.z);
    acc.w = fmaf(v, f1.y, acc.w);
}

__global__ void __launch_bounds__(256) spmm128_h_kernel(const int* __restrict__ edge_col,
                                                        const float* __restrict__ edge_val,
                                                        const __half* __restrict__ Z,
                                                        __half* __restrict__ out) {
    int gw   = (blockIdx.x * blockDim.x + threadIdx.x) >> 5;
    int lane = threadIdx.x & 31;
    if (gw >= N_NODES) return;
    int s = g_rowptr[gw];
    int e = g_rowptr[gw + 1];

    float4 acc = make_float4(0.f, 0.f, 0.f, 0.f);
    int i = s;
    for (; i + 4 <= e; i += 4) {
        int   c0 = __ldg(&edge_col[i + 0]);
        int   c1 = __ldg(&edge_col[i + 1]);
        int   c2 = __ldg(&edge_col[i + 2]);
        int   c3 = __ldg(&edge_col[i + 3]);
        float v0 = __ldg(&edge_val[i + 0]);
        float v1 = __ldg(&edge_val[i + 1]);
        float v2 = __ldg(&edge_val[i + 2]);
        float v3 = __ldg(&edge_val[i + 3]);
        uint2 z0 = *reinterpret_cast<const uint2*>(&Z[(size_t)c0 * H_DIM + lane * 4]);
        uint2 z1 = *reinterpret_cast<const uint2*>(&Z[(size_t)c1 * H_DIM + lane * 4]);
        uint2 z2 = *reinterpret_cast<const uint2*>(&Z[(size_t)c2 * H_DIM + lane * 4]);
        uint2 z3 = *reinterpret_cast<const uint2*>(&Z[(size_t)c3 * H_DIM + lane * 4]);
        fma_h4(acc, v0, z0);
        fma_h4(acc, v1, z1);
        fma_h4(acc, v2, z2);
        fma_h4(acc, v3, z3);
    }
    for (; i < e; i++) {
        int   col = __ldg(&edge_col[i]);
        float val = __ldg(&edge_val[i]);
        uint2 zz = *reinterpret_cast<const uint2*>(&Z[(size_t)col * H_DIM + lane * 4]);
        fma_h4(acc, val, zz);
    }
    acc.x = fmaxf(acc.x, 0.f);
    acc.y = fmaxf(acc.y, 0.f);
    acc.z = fmaxf(acc.z, 0.f);
    acc.w = fmaxf(acc.w, 0.f);
    __half2 o0 = __floats2half2_rn(acc.x, acc.y);
    __half2 o1 = __floats2half2_rn(acc.z, acc.w);
    uint2 ov = make_uint2(*reinterpret_cast<uint32_t*>(&o0), *reinterpret_cast<uint32_t*>(&o1));
    *reinterpret_cast<uint2*>(&out[(size_t)gw * H_DIM + lane * 4]) = ov;
}

// ---------------------------------------------------------------------------
// Final SpMM (F=64), fp16 gather, fused row softmax, fp32 output.
// ---------------------------------------------------------------------------
__global__ void __launch_bounds__(256) spmm64_softmax_kernel(const int* __restrict__ edge_col,
                                                             const float* __restrict__ edge_val,
                                                             const __half* __restrict__ Z,
                                                             float* __restrict__ out) {
    int gw   = (blockIdx.x * blockDim.x + threadIdx.x) >> 5;
    int lane = threadIdx.x & 31;
    if (gw >= N_NODES) return;
    int s = g_rowptr[gw];
    int e = g_rowptr[gw + 1];

    float a0 = 0.f, a1 = 0.f;
    int i = s;
    for (; i + 4 <= e; i += 4) {
#pragma unroll
        for (int u = 0; u < 4; u++) {
            int   col = __ldg(&edge_col[i + u]);
            float val = __ldg(&edge_val[i + u]);
            uint32_t zz = *reinterpret_cast<const uint32_t*>(&Z[(size_t)col * F_DIM + lane * 2]);
            float2 f = __half22float2(*reinterpret_cast<__half2*>(&zz));
            a0 = fmaf(val, f.x, a0);
            a1 = fmaf(val, f.y, a1);
        }
    }
    for (; i < e; i++) {
        int   col = __ldg(&edge_col[i]);
        float val = __ldg(&edge_val[i]);
        uint32_t zz = *reinterpret_cast<const uint32_t*>(&Z[(size_t)col * F_DIM + lane * 2]);
        float2 f = __half22float2(*reinterpret_cast<__half2*>(&zz));
        a0 = fmaf(val, f.x, a0);
        a1 = fmaf(val, f.y, a1);
    }
    float m = fmaxf(a0, a1);
#pragma unroll
    for (int off = 16; off > 0; off >>= 1)
        m = fmaxf(m, __shfl_xor_sync(0xFFFFFFFFu, m, off));
    float e0 = expf(a0 - m);
    float e1 = expf(a1 - m);
    float ssum = e0 + e1;
#pragma unroll
    for (int off = 16; off > 0; off >>= 1)
        ssum += __shfl_xor_sync(0xFFFFFFFFu, ssum, off);
    float inv = 1.0f / ssum;
    *reinterpret_cast<float2*>(&out[(size_t)gw * F_DIM + lane * 2]) =
        make_float2(e0 * inv, e1 * inv);
}

// ---------------------------------------------------------------------------
// Launch
// ---------------------------------------------------------------------------
extern "C" void kernel_launch(void* const* d_in, const int* in_sizes, int n_in,
                              void* d_out, int out_size) {
    const float* X        = (const float*)d_in[0];
    const int*   edge_row = (const int*)d_in[1];
    const int*   edge_col = (const int*)d_in[2];
    const float* edge_val = (const float*)d_in[3];
    const float* W0       = (const float*)d_in[4];
    const float* Wh0      = (const float*)d_in[5];
    const float* W1       = (const float*)d_in[6];
    float*       out      = (float*)d_out;

    __half *h1, *h2;
    cudaGetSymbolAddress((void**)&h1, g_hbuf1);
    cudaGetSymbolAddress((void**)&h2, g_hbuf2);

    constexpr int SMEM_F32_128 = 3 * (128 * 144 + 128 * 144);   // 110592 (L0)
    constexpr int SMEM_F16_128 = 3 * (128 * 80 + 128 * 144);    // 86016  (L1)
    constexpr int SMEM_F16_64  = 3 * (128 * 80 + 64 * 144);     // 58368  (L2)
    cudaFuncSetAttribute((const void*)gemm_tf32p<128, 256, float>,
                         cudaFuncAttributeMaxDynamicSharedMemorySize, SMEM_F32_128);
    cudaFuncSetAttribute((const void*)gemm_tf32p<128, 128, __half>,
                         cudaFuncAttributeMaxDynamicSharedMemorySize, SMEM_F16_128);
    cudaFuncSetAttribute((const void*)gemm_tf32p<64, 128, __half>,
                         cudaFuncAttributeMaxDynamicSharedMemorySize, SMEM_F16_64);

    const int gemm_grid = (N_NODES + 127) / 128;       // 782
    const int spmm_grid = (N_NODES * 32 + 255) / 256;  // 12500

    rowptr_kernel<<<(N_NODES + 1 + 255) / 256, 256>>>(edge_row);

    // Layer 0: h1 = (h16) X @ W0^T ; h2 = (h16) relu(A @ h1)
    gemm_tf32p<128, 256, float><<<gemm_grid, 256, SMEM_F32_128>>>(X, W0, h1, N_NODES);
    spmm128_h_kernel<<<spmm_grid, 256>>>(edge_col, edge_val, h1, h2);

    // Hidden: h1 = h2 @ Wh0^T ; h2 = relu(A @ h1)
    gemm_tf32p<128, 128, __half><<<gemm_grid, 256, SMEM_F16_128>>>(h2, Wh0, h1, N_NODES);
    spmm128_h_kernel<<<spmm_grid, 256>>>(edge_col, edge_val, h1, h2);

    // Output: h1 = h2 @ W1^T ; out = softmax(A @ h1)
    gemm_tf32p<64, 128, __half><<<gemm_grid, 256, SMEM_F16_64>>>(h2, W1, h1, N_NODES);
    spmm64_softmax_kernel<<<spmm_grid, 256>>>(edge_col, edge_val, h1, out);
}

// round 9
// speedup vs baseline: 1.1348x; 1.0386x over previous
#include <cuda_runtime.h>
#include <cuda_fp16.h>
#include <math.h>
#include <stdint.h>

#define N_NODES 100000
#define E_EDGES 1600000
#define C_DIM 256
#define H_DIM 128
#define F_DIM 64

// Scratch (__device__ globals; no allocation allowed)
__device__ __half g_hbuf1[N_NODES * H_DIM];   // GEMM outputs (pre-aggregation)
__device__ __half g_hbuf2[N_NODES * H_DIM];   // SpMM outputs (activations)
__device__ __half g_Xh[N_NODES * C_DIM];      // fp16 cast of X
__device__ __half g_Wh[57344];                // fp16 W0 | Wh0 | W1
__device__ int    g_rowptr[N_NODES + 1];

// ---------------------------------------------------------------------------
// Helpers
// ---------------------------------------------------------------------------
__device__ __forceinline__ uint32_t smem_u32(const void* p) {
    uint32_t a;
    asm("{ .reg .u64 t; cvta.to.shared.u64 t, %1; cvt.u32.u64 %0, t; }" : "=r"(a) : "l"(p));
    return a;
}
__device__ __forceinline__ void ldsm_x4(uint32_t (&r)[4], uint32_t addr) {
    asm volatile("ldmatrix.sync.aligned.m8n8.x4.shared.b16 {%0,%1,%2,%3}, [%4];"
                 : "=r"(r[0]), "=r"(r[1]), "=r"(r[2]), "=r"(r[3]) : "r"(addr));
}
__device__ __forceinline__ void mma_f16(float (&d)[4], const uint32_t (&a)[4],
                                        uint32_t b0, uint32_t b1) {
    asm volatile(
        "mma.sync.aligned.m16n8k16.row.col.f32.f16.f16.f32 "
        "{%0,%1,%2,%3}, {%4,%5,%6,%7}, {%8,%9}, {%0,%1,%2,%3};"
        : "+f"(d[0]), "+f"(d[1]), "+f"(d[2]), "+f"(d[3])
        : "r"(a[0]), "r"(a[1]), "r"(a[2]), "r"(a[3]), "r"(b0), "r"(b1));
}
__device__ __forceinline__ void cp_async16(uint32_t dst, const void* src, int srcsize) {
    asm volatile("cp.async.cg.shared.global [%0], [%1], 16, %2;"
                 :: "r"(dst), "l"(src), "r"(srcsize));
}
#define CP_COMMIT() asm volatile("cp.async.commit_group;" ::: "memory")
template<int NW> __device__ __forceinline__ void cp_wait() {
    asm volatile("cp.async.wait_group %0;" :: "n"(NW) : "memory");
}

// ---------------------------------------------------------------------------
// Prep kernels: rowptr, fp32 -> fp16 cast
// ---------------------------------------------------------------------------
__global__ void rowptr_kernel(const int* __restrict__ edge_row) {
    int i = blockIdx.x * blockDim.x + threadIdx.x;
    if (i > N_NODES) return;
    int lo = 0, hi = E_EDGES;
    while (lo < hi) {
        int mid = (lo + hi) >> 1;
        if (edge_row[mid] < i) lo = mid + 1;
        else hi = mid;
    }
    g_rowptr[i] = lo;
}

__global__ void cast_h_kernel(const float* __restrict__ src,
                              __half* __restrict__ dst, int n4) {
    int i = blockIdx.x * blockDim.x + threadIdx.x;
    if (i >= n4) return;
    float4 v = reinterpret_cast<const float4*>(src)[i];
    __half2 h0 = __floats2half2_rn(v.x, v.y);
    __half2 h1 = __floats2half2_rn(v.z, v.w);
    uint2 o = make_uint2(*reinterpret_cast<uint32_t*>(&h0),
                         *reinterpret_cast<uint32_t*>(&h1));
    reinterpret_cast<uint2*>(dst)[i] = o;
}

// ---------------------------------------------------------------------------
// fp16 HMMA GEMM, 3-stage cp.async pipeline, one barrier per BK=64 chunk:
//   out[m][n] = (half) sum_k A[m][k] * W[n][k]   (A, W fp16; f32 accumulate)
// BM=128, BK=64, 256 threads (8 warps), 2 CTAs/SM.
// Smem rows: 64 halves + 8 pad = 144B stride (rows hit distinct bank groups).
// Fragment scheme identical to the R3-verified bf16 kernel.
// ---------------------------------------------------------------------------
template<int N, int K>
__global__ void __launch_bounds__(256, 2) gemm_h(const __half* __restrict__ A,
                                                 const __half* __restrict__ W,
                                                 __half* __restrict__ out, int M) {
    constexpr int BM = 128;
    constexpr int LDS = 144;                   // bytes per smem row
    constexpr int ABYTES = BM * LDS;           // 18432
    constexpr int WBYTES = N * LDS;
    constexpr int STAGEB = ABYTES + WBYTES;
    constexpr int NC = K / 64;
    constexpr int WCOLS = N / 32;
    constexpr int WROWS = 8 / WCOLS;
    constexpr int WTM = BM / WROWS;            // 64 or 32
    constexpr int MT = WTM / 16;               // 4 or 2

    extern __shared__ char smem[];
    const uint32_t sb = smem_u32(smem);

    const int tid  = threadIdx.x;
    const int wid  = tid >> 5;
    const int lane = tid & 31;
    const int wm   = (wid / WCOLS) * WTM;
    const int wn   = (wid % WCOLS) * 32;
    const int bm   = blockIdx.x * BM;
    const int arows = min(BM, M - bm);

    const int lrow  = lane & 15;
    const int lcolb = (lane >> 4) * 16;

    float acc[MT][4][4];
#pragma unroll
    for (int i = 0; i < MT; i++)
#pragma unroll
        for (int j = 0; j < 4; j++)
#pragma unroll
            for (int c = 0; c < 4; c++) acc[i][j][c] = 0.f;

    auto fill = [&](int s, int k0) {
        const uint32_t base = sb + (uint32_t)(s * STAGEB);
#pragma unroll
        for (int idx = tid; idx < BM * 8; idx += 256) {      // 4 iters
            int row = idx >> 3, g = idx & 7;
            int sz = (row < arows) ? 16 : 0;
            cp_async16(base + (uint32_t)(row * LDS + g * 16),
                       &A[(size_t)(bm + row) * K + k0 + g * 8], sz);
        }
#pragma unroll
        for (int idx = tid; idx < N * 8; idx += 256) {       // 4 or 2 iters
            int row = idx >> 3, g = idx & 7;
            cp_async16(base + (uint32_t)(ABYTES + row * LDS + g * 16),
                       &W[(size_t)row * K + k0 + g * 8], 16);
        }
        CP_COMMIT();
    };

    fill(0, 0);
    if (NC > 1) fill(1, 64);

    for (int kc = 0; kc < NC; kc++) {
        if (kc + 1 < NC) cp_wait<1>(); else cp_wait<0>();
        __syncthreads();

        const uint32_t st = sb + (uint32_t)((kc % 3) * STAGEB);
        const uint32_t aB = st;
        const uint32_t wB = st + ABYTES;

#pragma unroll
        for (int ks = 0; ks < 4; ks++) {                     // 4 k16 steps
            const uint32_t cb = (uint32_t)(ks * 32 + lcolb);
            uint32_t af[MT][4];
#pragma unroll
            for (int mt = 0; mt < MT; mt++)
                ldsm_x4(af[mt], aB + (uint32_t)((wm + mt * 16 + lrow) * LDS) + cb);
            uint32_t bf[2][4];
#pragma unroll
            for (int np = 0; np < 2; np++)
                ldsm_x4(bf[np], wB + (uint32_t)((wn + np * 16 + lrow) * LDS) + cb);
#pragma unroll
            for (int mt = 0; mt < MT; mt++)
#pragma unroll
                for (int nt = 0; nt < 4; nt++) {
                    int np = nt >> 1, h = nt & 1;
                    mma_f16(acc[mt][nt], af[mt], bf[np][h], bf[np][h + 2]);
                }
        }

        if (kc + 2 < NC) fill((kc + 2) % 3, (kc + 2) * 64);
    }

    // Epilogue: fp16 store
#pragma unroll
    for (int mt = 0; mt < MT; mt++) {
#pragma unroll
        for (int nt = 0; nt < 4; nt++) {
            int r0 = wm + mt * 16 + (lane >> 2);
            int c0 = wn + nt * 8 + (lane & 3) * 2;
            if (r0 < arows)
                *reinterpret_cast<__half2*>(&out[(size_t)(bm + r0) * N + c0]) =
                    __floats2half2_rn(acc[mt][nt][0], acc[mt][nt][1]);
            if (r0 + 8 < arows)
                *reinterpret_cast<__half2*>(&out[(size_t)(bm + r0 + 8) * N + c0]) =
                    __floats2half2_rn(acc[mt][nt][2], acc[mt][nt][3]);
        }
    }
}

// ---------------------------------------------------------------------------
// SpMM (H=128), fp16 gather / fp32 accumulate / ReLU / fp16 store.
// ---------------------------------------------------------------------------
__device__ __forceinline__ void fma_h4(float4& acc, float v, uint2 zz) {
    float2 f0 = __half22float2(*reinterpret_cast<__half2*>(&zz.x));
    float2 f1 = __half22float2(*reinterpret_cast<__half2*>(&zz.y));
    acc.x = fmaf(v, f0.x, acc.x);
    acc.y = fmaf(v, f0.y, acc.y);
    acc.z = fmaf(v, f1.x, acc.z);
    acc.w = fmaf(v, f1.y, acc.w);
}

__global__ void __launch_bounds__(256) spmm128_h_kernel(const int* __restrict__ edge_col,
                                                        const float* __restrict__ edge_val,
                                                        const __half* __restrict__ Z,
                                                        __half* __restrict__ out) {
    int gw   = (blockIdx.x * blockDim.x + threadIdx.x) >> 5;
    int lane = threadIdx.x & 31;
    if (gw >= N_NODES) return;
    int s = g_rowptr[gw];
    int e = g_rowptr[gw + 1];

    float4 acc = make_float4(0.f, 0.f, 0.f, 0.f);
    int i = s;
    for (; i + 4 <= e; i += 4) {
        int   c0 = __ldg(&edge_col[i + 0]);
        int   c1 = __ldg(&edge_col[i + 1]);
        int   c2 = __ldg(&edge_col[i + 2]);
        int   c3 = __ldg(&edge_col[i + 3]);
        float v0 = __ldg(&edge_val[i + 0]);
        float v1 = __ldg(&edge_val[i + 1]);
        float v2 = __ldg(&edge_val[i + 2]);
        float v3 = __ldg(&edge_val[i + 3]);
        uint2 z0 = *reinterpret_cast<const uint2*>(&Z[(size_t)c0 * H_DIM + lane * 4]);
        uint2 z1 = *reinterpret_cast<const uint2*>(&Z[(size_t)c1 * H_DIM + lane * 4]);
        uint2 z2 = *reinterpret_cast<const uint2*>(&Z[(size_t)c2 * H_DIM + lane * 4]);
        uint2 z3 = *reinterpret_cast<const uint2*>(&Z[(size_t)c3 * H_DIM + lane * 4]);
        fma_h4(acc, v0, z0);
        fma_h4(acc, v1, z1);
        fma_h4(acc, v2, z2);
        fma_h4(acc, v3, z3);
    }
    for (; i < e; i++) {
        int   col = __ldg(&edge_col[i]);
        float val = __ldg(&edge_val[i]);
        uint2 zz = *reinterpret_cast<const uint2*>(&Z[(size_t)col * H_DIM + lane * 4]);
        fma_h4(acc, val, zz);
    }
    acc.x = fmaxf(acc.x, 0.f);
    acc.y = fmaxf(acc.y, 0.f);
    acc.z = fmaxf(acc.z, 0.f);
    acc.w = fmaxf(acc.w, 0.f);
    __half2 o0 = __floats2half2_rn(acc.x, acc.y);
    __half2 o1 = __floats2half2_rn(acc.z, acc.w);
    uint2 ov = make_uint2(*reinterpret_cast<uint32_t*>(&o0), *reinterpret_cast<uint32_t*>(&o1));
    *reinterpret_cast<uint2*>(&out[(size_t)gw * H_DIM + lane * 4]) = ov;
}

// ---------------------------------------------------------------------------
// Final SpMM (F=64), fp16 gather, fused row softmax, fp32 output.
// ---------------------------------------------------------------------------
__global__ void __launch_bounds__(256) spmm64_softmax_kernel(const int* __restrict__ edge_col,
                                                             const float* __restrict__ edge_val,
                                                             const __half* __restrict__ Z,
                                                             float* __restrict__ out) {
    int gw   = (blockIdx.x * blockDim.x + threadIdx.x) >> 5;
    int lane = threadIdx.x & 31;
    if (gw >= N_NODES) return;
    int s = g_rowptr[gw];
    int e = g_rowptr[gw + 1];

    float a0 = 0.f, a1 = 0.f;
    int i = s;
    for (; i + 4 <= e; i += 4) {
#pragma unroll
        for (int u = 0; u < 4; u++) {
            int   col = __ldg(&edge_col[i + u]);
            float val = __ldg(&edge_val[i + u]);
            uint32_t zz = *reinterpret_cast<const uint32_t*>(&Z[(size_t)col * F_DIM + lane * 2]);
            float2 f = __half22float2(*reinterpret_cast<__half2*>(&zz));
            a0 = fmaf(val, f.x, a0);
            a1 = fmaf(val, f.y, a1);
        }
    }
    for (; i < e; i++) {
        int   col = __ldg(&edge_col[i]);
        float val = __ldg(&edge_val[i]);
        uint32_t zz = *reinterpret_cast<const uint32_t*>(&Z[(size_t)col * F_DIM + lane * 2]);
        float2 f = __half22float2(*reinterpret_cast<__half2*>(&zz));
        a0 = fmaf(val, f.x, a0);
        a1 = fmaf(val, f.y, a1);
    }
    float m = fmaxf(a0, a1);
#pragma unroll
    for (int off = 16; off > 0; off >>= 1)
        m = fmaxf(m, __shfl_xor_sync(0xFFFFFFFFu, m, off));
    float e0 = expf(a0 - m);
    float e1 = expf(a1 - m);
    float ssum = e0 + e1;
#pragma unroll
    for (int off = 16; off > 0; off >>= 1)
        ssum += __shfl_xor_sync(0xFFFFFFFFu, ssum, off);
    float inv = 1.0f / ssum;
    *reinterpret_cast<float2*>(&out[(size_t)gw * F_DIM + lane * 2]) =
        make_float2(e0 * inv, e1 * inv);
}

// ---------------------------------------------------------------------------
// Launch
// ---------------------------------------------------------------------------
extern "C" void kernel_launch(void* const* d_in, const int* in_sizes, int n_in,
                              void* d_out, int out_size) {
    const float* X        = (const float*)d_in[0];
    const int*   edge_row = (const int*)d_in[1];
    const int*   edge_col = (const int*)d_in[2];
    const float* edge_val = (const float*)d_in[3];
    const float* W0       = (const float*)d_in[4];
    const float* Wh0      = (const float*)d_in[5];
    const float* W1       = (const float*)d_in[6];
    float*       out      = (float*)d_out;

    __half *h1, *h2, *Xh, *Wh;
    cudaGetSymbolAddress((void**)&h1, g_hbuf1);
    cudaGetSymbolAddress((void**)&h2, g_hbuf2);
    cudaGetSymbolAddress((void**)&Xh, g_Xh);
    cudaGetSymbolAddress((void**)&Wh, g_Wh);

    constexpr int SMEM_128 = 3 * (128 + 128) * 144;   // 110592
    constexpr int SMEM_64  = 3 * (128 + 64) * 144;    // 82944
    cudaFuncSetAttribute((const void*)gemm_h<128, 256>,
                         cudaFuncAttributeMaxDynamicSharedMemorySize, SMEM_128);
    cudaFuncSetAttribute((const void*)gemm_h<128, 128>,
                         cudaFuncAttributeMaxDynamicSharedMemorySize, SMEM_128);
    cudaFuncSetAttribute((const void*)gemm_h<64, 128>,
                         cudaFuncAttributeMaxDynamicSharedMemorySize, SMEM_64);

    const int gemm_grid = (N_NODES + 127) / 128;       // 782
    const int spmm_grid = (N_NODES * 32 + 255) / 256;  // 12500

    rowptr_kernel<<<(N_NODES + 1 + 255) / 256, 256>>>(edge_row);

    // One-time fp16 casts
    cast_h_kernel<<<(N_NODES * C_DIM / 4 + 255) / 256, 256>>>(X, Xh, N_NODES * C_DIM / 4);
    cast_h_kernel<<<(32768 / 4 + 255) / 256, 256>>>(W0,  Wh,         32768 / 4);
    cast_h_kernel<<<(16384 / 4 + 255) / 256, 256>>>(Wh0, Wh + 32768, 16384 / 4);
    cast_h_kernel<<<(8192 / 4 + 255) / 256, 256>>>(W1,  Wh + 49152, 8192 / 4);

    // Layer 0: h1 = Xh @ W0h^T ; h2 = relu(A @ h1)
    gemm_h<128, 256><<<gemm_grid, 256, SMEM_128>>>(Xh, Wh, h1, N_NODES);
    spmm128_h_kernel<<<spmm_grid, 256>>>(edge_col, edge_val, h1, h2);

    // Hidden: h1 = h2 @ Wh0h^T ; h2 = relu(A @ h1)
    gemm_h<128, 128><<<gemm_grid, 256, SMEM_128>>>(h2, Wh + 32768, h1, N_NODES);
    spmm128_h_kernel<<<spmm_grid, 256>>>(edge_col, edge_val, h1, h2);

    // Output: h1 = h2 @ W1h^T ; out = softmax(A @ h1)
    gemm_h<64, 128><<<gemm_grid, 256, SMEM_64>>>(h2, Wh + 49152, h1, N_NODES);
    spmm64_softmax_kernel<<<spmm_grid, 256>>>(edge_col, edge_val, h1, out);
}

// round 10
// speedup vs baseline: 1.2698x; 1.1190x over previous
#include <cuda_runtime.h>
#include <cuda_fp16.h>
#include <math.h>
#include <stdint.h>

#define N_NODES 100000
#define E_EDGES 1600000
#define C_DIM 256
#define H_DIM 128
#define F_DIM 64

// Scratch (__device__ globals; no allocation allowed)
__device__ __half g_hbuf1[N_NODES * H_DIM];   // GEMM outputs (pre-aggregation)
__device__ __half g_hbuf2[N_NODES * H_DIM];   // SpMM outputs (activations)
__device__ __half g_Wh[57344];                // fp16 W0 | Wh0 | W1
__device__ int    g_rowptr[N_NODES + 1];

// ---------------------------------------------------------------------------
// Helpers
// ---------------------------------------------------------------------------
__device__ __forceinline__ uint32_t smem_u32(const void* p) {
    uint32_t a;
    asm("{ .reg .u64 t; cvta.to.shared.u64 t, %1; cvt.u32.u64 %0, t; }" : "=r"(a) : "l"(p));
    return a;
}
__device__ __forceinline__ void ldsm_x4(uint32_t (&r)[4], uint32_t addr) {
    asm volatile("ldmatrix.sync.aligned.m8n8.x4.shared.b16 {%0,%1,%2,%3}, [%4];"
                 : "=r"(r[0]), "=r"(r[1]), "=r"(r[2]), "=r"(r[3]) : "r"(addr));
}
__device__ __forceinline__ void mma_f16(float (&d)[4], const uint32_t (&a)[4],
                                        uint32_t b0, uint32_t b1) {
    asm volatile(
        "mma.sync.aligned.m16n8k16.row.col.f32.f16.f16.f32 "
        "{%0,%1,%2,%3}, {%4,%5,%6,%7}, {%8,%9}, {%0,%1,%2,%3};"
        : "+f"(d[0]), "+f"(d[1]), "+f"(d[2]), "+f"(d[3])
        : "r"(a[0]), "r"(a[1]), "r"(a[2]), "r"(a[3]), "r"(b0), "r"(b1));
}
__device__ __forceinline__ void cp_async16(uint32_t dst, const void* src, int srcsize) {
    asm volatile("cp.async.cg.shared.global [%0], [%1], 16, %2;"
                 :: "r"(dst), "l"(src), "r"(srcsize));
}
#define CP_COMMIT() asm volatile("cp.async.commit_group;" ::: "memory")
template<int NW> __device__ __forceinline__ void cp_wait() {
    asm volatile("cp.async.wait_group %0;" :: "n"(NW) : "memory");
}
__device__ __forceinline__ uint32_t pack_h2(float2 v) {
    __half2 h = __floats2half2_rn(v.x, v.y);
    return *reinterpret_cast<uint32_t*>(&h);
}

// ---------------------------------------------------------------------------
// Prep: rowptr + merged weight cast (W0|Wh0|W1 -> g_Wh)
// ---------------------------------------------------------------------------
__global__ void rowptr_kernel(const int* __restrict__ edge_row) {
    int i = blockIdx.x * blockDim.x + threadIdx.x;
    if (i > N_NODES) return;
    int lo = 0, hi = E_EDGES;
    while (lo < hi) {
        int mid = (lo + hi) >> 1;
        if (edge_row[mid] < i) lo = mid + 1;
        else hi = mid;
    }
    g_rowptr[i] = lo;
}

__global__ void wcast_kernel(const float* __restrict__ W0,
                             const float* __restrict__ Wh0,
                             const float* __restrict__ W1,
                             __half* __restrict__ dst) {
    int i = blockIdx.x * blockDim.x + threadIdx.x;   // float4 group index
    if (i >= 14336) return;                          // 57344 / 4
    const float* src;
    int j;
    if (i < 8192)       { src = W0;  j = i; }
    else if (i < 12288) { src = Wh0; j = i - 8192; }
    else                { src = W1;  j = i - 12288; }
    float4 v = reinterpret_cast<const float4*>(src)[j];
    uint2 o = make_uint2(pack_h2(make_float2(v.x, v.y)), pack_h2(make_float2(v.z, v.w)));
    reinterpret_cast<uint2*>(dst)[i] = o;
}

// ---------------------------------------------------------------------------
// Layer-0 GEMM: A fp32 (staged raw, cvt on fragment load), W fp16 (ldmatrix).
//   out[m][n] = (half) sum_k A[m][k] * W[n][k]
// BM=128, N=128, BK=32, K=256. 256 threads, 3-stage cp.async, 2 CTAs/SM.
// A smem rows: 40 floats (160B) -> LDS.64 conflict-free per 16-lane phase.
// W smem rows: 40 halves (80B) -> ldmatrix conflict-free.
// ---------------------------------------------------------------------------
__global__ void __launch_bounds__(256, 2) gemm_l0(const float* __restrict__ A,
                                                  const __half* __restrict__ W,
                                                  __half* __restrict__ out, int M) {
    constexpr int BM = 128, N = 128, K = 256, BK = 32;
    constexpr int NC = K / BK;                  // 8
    constexpr int LDSA = 40;                    // floats per A row (160B)
    constexpr int ABYTES = BM * LDSA * 4;       // 20480
    constexpr int LDSW = 80;                    // bytes per W row
    constexpr int WBYTES = N * LDSW;            // 10240
    constexpr int STAGEB = ABYTES + WBYTES;     // 30720 (x3 = 92160)
    constexpr int MT = 4;                       // warp grid 2x4, warp tile 64x32

    extern __shared__ char smem[];
    const uint32_t sb = smem_u32(smem);

    const int tid  = threadIdx.x;
    const int wid  = tid >> 5;
    const int lane = tid & 31;
    const int wm   = (wid >> 2) * 64;
    const int wn   = (wid & 3) * 32;
    const int bm   = blockIdx.x * BM;
    const int arows = min(BM, M - bm);

    const int fr    = lane >> 2;
    const int fc    = lane & 3;
    const int lrow  = lane & 15;
    const int lcolb = (lane >> 4) * 16;

    float acc[MT][4][4];
#pragma unroll
    for (int i = 0; i < MT; i++)
#pragma unroll
        for (int j = 0; j < 4; j++)
#pragma unroll
            for (int c = 0; c < 4; c++) acc[i][j][c] = 0.f;

    auto fill = [&](int s, int k0) {
        const uint32_t base = sb + (uint32_t)(s * STAGEB);
#pragma unroll
        for (int idx = tid; idx < BM * 8; idx += 256) {      // A: 8x16B per row
            int row = idx >> 3, g = idx & 7;
            int sz = (row < arows) ? 16 : 0;
            cp_async16(base + (uint32_t)(row * 160 + g * 16),
                       &A[(size_t)(bm + row) * K + k0 + g * 4], sz);
        }
#pragma unroll
        for (int idx = tid; idx < N * 4; idx += 256) {       // W: 4x16B per row
            int row = idx >> 2, g = idx & 3;
            cp_async16(base + (uint32_t)(ABYTES + row * LDSW + g * 16),
                       &W[(size_t)row * K + k0 + g * 8], 16);
        }
        CP_COMMIT();
    };

    fill(0, 0);
    fill(1, BK);

    for (int kc = 0; kc < NC; kc++) {
        if (kc + 1 < NC) cp_wait<1>(); else cp_wait<0>();
        __syncthreads();

        const char*  stg = smem + (kc % 3) * STAGEB;
        const float* sA  = reinterpret_cast<const float*>(stg);
        const uint32_t wB = sb + (uint32_t)((kc % 3) * STAGEB + ABYTES);

#pragma unroll
        for (int ks = 0; ks < 2; ks++) {                     // 2 k16 steps
            uint32_t af[MT][4];
#pragma unroll
            for (int mt = 0; mt < MT; mt++) {
                int base = (wm + mt * 16 + fr) * LDSA + ks * 16 + fc * 2;
                float2 v0 = *reinterpret_cast<const float2*>(&sA[base]);
                float2 v1 = *reinterpret_cast<const float2*>(&sA[base + 8 * LDSA]);
                float2 v2 = *reinterpret_cast<const float2*>(&sA[base + 8]);
                float2 v3 = *reinterpret_cast<const float2*>(&sA[base + 8 * LDSA + 8]);
                af[mt][0] = pack_h2(v0);
                af[mt][1] = pack_h2(v1);
                af[mt][2] = pack_h2(v2);
                af[mt][3] = pack_h2(v3);
            }
            uint32_t bf[2][4];
#pragma unroll
            for (int np = 0; np < 2; np++)
                ldsm_x4(bf[np], wB + (uint32_t)((wn + np * 16 + lrow) * LDSW
                                                + ks * 32 + lcolb));
#pragma unroll
            for (int mt = 0; mt < MT; mt++)
#pragma unroll
                for (int nt = 0; nt < 4; nt++) {
                    int np = nt >> 1, h = nt & 1;
                    mma_f16(acc[mt][nt], af[mt], bf[np][h], bf[np][h + 2]);
                }
        }

        if (kc + 2 < NC) fill((kc + 2) % 3, (kc + 2) * BK);
    }

    // Epilogue: fp16 store
#pragma unroll
    for (int mt = 0; mt < MT; mt++) {
#pragma unroll
        for (int nt = 0; nt < 4; nt++) {
            int r0 = wm + mt * 16 + fr;
            int c0 = wn + nt * 8 + fc * 2;
            if (r0 < arows)
                *reinterpret_cast<__half2*>(&out[(size_t)(bm + r0) * N + c0]) =
                    __floats2half2_rn(acc[mt][nt][0], acc[mt][nt][1]);
            if (r0 + 8 < arows)
                *reinterpret_cast<__half2*>(&out[(size_t)(bm + r0 + 8) * N + c0]) =
                    __floats2half2_rn(acc[mt][nt][2], acc[mt][nt][3]);
        }
    }
}

// ---------------------------------------------------------------------------
// fp16 HMMA GEMM (layers 1-2), 3-stage cp.async, BK=64 — unchanged from R9.
// ---------------------------------------------------------------------------
template<int N, int K>
__global__ void __launch_bounds__(256, 2) gemm_h(const __half* __restrict__ A,
                                                 const __half* __restrict__ W,
                                                 __half* __restrict__ out, int M) {
    constexpr int BM = 128;
    constexpr int LDS = 144;
    constexpr int ABYTES = BM * LDS;
    constexpr int WBYTES = N * LDS;
    constexpr int STAGEB = ABYTES + WBYTES;
    constexpr int NC = K / 64;
    constexpr int WCOLS = N / 32;
    constexpr int WTM = BM / (8 / WCOLS);
    constexpr int MT = WTM / 16;

    extern __shared__ char smem[];
    const uint32_t sb = smem_u32(smem);

    const int tid  = threadIdx.x;
    const int wid  = tid >> 5;
    const int lane = tid & 31;
    const int wm   = (wid / WCOLS) * WTM;
    const int wn   = (wid % WCOLS) * 32;
    const int bm   = blockIdx.x * BM;
    const int arows = min(BM, M - bm);

    const int lrow  = lane & 15;
    const int lcolb = (lane >> 4) * 16;

    float acc[MT][4][4];
#pragma unroll
    for (int i = 0; i < MT; i++)
#pragma unroll
        for (int j = 0; j < 4; j++)
#pragma unroll
            for (int c = 0; c < 4; c++) acc[i][j][c] = 0.f;

    auto fill = [&](int s, int k0) {
        const uint32_t base = sb + (uint32_t)(s * STAGEB);
#pragma unroll
        for (int idx = tid; idx < BM * 8; idx += 256) {
            int row = idx >> 3, g = idx & 7;
            int sz = (row < arows) ? 16 : 0;
            cp_async16(base + (uint32_t)(row * LDS + g * 16),
                       &A[(size_t)(bm + row) * K + k0 + g * 8], sz);
        }
#pragma unroll
        for (int idx = tid; idx < N * 8; idx += 256) {
            int row = idx >> 3, g = idx & 7;
            cp_async16(base + (uint32_t)(ABYTES + row * LDS + g * 16),
                       &W[(size_t)row * K + k0 + g * 8], 16);
        }
        CP_COMMIT();
    };

    fill(0, 0);
    if (NC > 1) fill(1, 64);

    for (int kc = 0; kc < NC; kc++) {
        if (kc + 1 < NC) cp_wait<1>(); else cp_wait<0>();
        __syncthreads();

        const uint32_t st = sb + (uint32_t)((kc % 3) * STAGEB);
        const uint32_t aB = st;
        const uint32_t wB = st + ABYTES;

#pragma unroll
        for (int ks = 0; ks < 4; ks++) {
            const uint32_t cb = (uint32_t)(ks * 32 + lcolb);
            uint32_t af[MT][4];
#pragma unroll
            for (int mt = 0; mt < MT; mt++)
                ldsm_x4(af[mt], aB + (uint32_t)((wm + mt * 16 + lrow) * LDS) + cb);
            uint32_t bf[2][4];
#pragma unroll
            for (int np = 0; np < 2; np++)
                ldsm_x4(bf[np], wB + (uint32_t)((wn + np * 16 + lrow) * LDS) + cb);
#pragma unroll
            for (int mt = 0; mt < MT; mt++)
#pragma unroll
                for (int nt = 0; nt < 4; nt++) {
                    int np = nt >> 1, h = nt & 1;
                    mma_f16(acc[mt][nt], af[mt], bf[np][h], bf[np][h + 2]);
                }
        }

        if (kc + 2 < NC) fill((kc + 2) % 3, (kc + 2) * 64);
    }

#pragma unroll
    for (int mt = 0; mt < MT; mt++) {
#pragma unroll
        for (int nt = 0; nt < 4; nt++) {
            int r0 = wm + mt * 16 + (lane >> 2);
            int c0 = wn + nt * 8 + (lane & 3) * 2;
            if (r0 < arows)
                *reinterpret_cast<__half2*>(&out[(size_t)(bm + r0) * N + c0]) =
                    __floats2half2_rn(acc[mt][nt][0], acc[mt][nt][1]);
            if (r0 + 8 < arows)
                *reinterpret_cast<__half2*>(&out[(size_t)(bm + r0 + 8) * N + c0]) =
                    __floats2half2_rn(acc[mt][nt][2], acc[mt][nt][3]);
        }
    }
}

// ---------------------------------------------------------------------------
// SpMM (H=128), fp16 gather / fp32 accumulate / ReLU / fp16 store.
// ---------------------------------------------------------------------------
__device__ __forceinline__ void fma_h4(float4& acc, float v, uint2 zz) {
    float2 f0 = __half22float2(*reinterpret_cast<__half2*>(&zz.x));
    float2 f1 = __half22float2(*reinterpret_cast<__half2*>(&zz.y));
    acc.x = fmaf(v, f0.x, acc.x);
    acc.y = fmaf(v, f0.y, acc.y);
    acc.z = fmaf(v, f1.x, acc.z);
    acc.w = fmaf(v, f1.y, acc.w);
}

__global__ void __launch_bounds__(256) spmm128_h_kernel(const int* __restrict__ edge_col,
                                                        const float* __restrict__ edge_val,
                                                        const __half* __restrict__ Z,
                                                        __half* __restrict__ out) {
    int gw   = (blockIdx.x * blockDim.x + threadIdx.x) >> 5;
    int lane = threadIdx.x & 31;
    if (gw >= N_NODES) return;
    int s = g_rowptr[gw];
    int e = g_rowptr[gw + 1];

    float4 acc = make_float4(0.f, 0.f, 0.f, 0.f);
    int i = s;
    for (; i + 4 <= e; i += 4) {
        int   c0 = __ldg(&edge_col[i + 0]);
        int   c1 = __ldg(&edge_col[i + 1]);
        int   c2 = __ldg(&edge_col[i + 2]);
        int   c3 = __ldg(&edge_col[i + 3]);
        float v0 = __ldg(&edge_val[i + 0]);
        float v1 = __ldg(&edge_val[i + 1]);
        float v2 = __ldg(&edge_val[i + 2]);
        float v3 = __ldg(&edge_val[i + 3]);
        uint2 z0 = *reinterpret_cast<const uint2*>(&Z[(size_t)c0 * H_DIM + lane * 4]);
        uint2 z1 = *reinterpret_cast<const uint2*>(&Z[(size_t)c1 * H_DIM + lane * 4]);
        uint2 z2 = *reinterpret_cast<const uint2*>(&Z[(size_t)c2 * H_DIM + lane * 4]);
        uint2 z3 = *reinterpret_cast<const uint2*>(&Z[(size_t)c3 * H_DIM + lane * 4]);
        fma_h4(acc, v0, z0);
        fma_h4(acc, v1, z1);
        fma_h4(acc, v2, z2);
        fma_h4(acc, v3, z3);
    }
    for (; i < e; i++) {
        int   col = __ldg(&edge_col[i]);
        float val = __ldg(&edge_val[i]);
        uint2 zz = *reinterpret_cast<const uint2*>(&Z[(size_t)col * H_DIM + lane * 4]);
        fma_h4(acc, val, zz);
    }
    acc.x = fmaxf(acc.x, 0.f);
    acc.y = fmaxf(acc.y, 0.f);
    acc.z = fmaxf(acc.z, 0.f);
    acc.w = fmaxf(acc.w, 0.f);
    uint2 ov = make_uint2(pack_h2(make_float2(acc.x, acc.y)),
                          pack_h2(make_float2(acc.z, acc.w)));
    *reinterpret_cast<uint2*>(&out[(size_t)gw * H_DIM + lane * 4]) = ov;
}

// ---------------------------------------------------------------------------
// Final SpMM (F=64), fp16 gather, fused row softmax, fp32 output.
// ---------------------------------------------------------------------------
__global__ void __launch_bounds__(256) spmm64_softmax_kernel(const int* __restrict__ edge_col,
                                                             const float* __restrict__ edge_val,
                                                             const __half* __restrict__ Z,
                                                             float* __restrict__ out) {
    int gw   = (blockIdx.x * blockDim.x + threadIdx.x) >> 5;
    int lane = threadIdx.x & 31;
    if (gw >= N_NODES) return;
    int s = g_rowptr[gw];
    int e = g_rowptr[gw + 1];

    float a0 = 0.f, a1 = 0.f;
    int i = s;
    for (; i + 4 <= e; i += 4) {
#pragma unroll
        for (int u = 0; u < 4; u++) {
            int   col = __ldg(&edge_col[i + u]);
            float val = __ldg(&edge_val[i + u]);
            uint32_t zz = *reinterpret_cast<const uint32_t*>(&Z[(size_t)col * F_DIM + lane * 2]);
            float2 f = __half22float2(*reinterpret_cast<__half2*>(&zz));
            a0 = fmaf(val, f.x, a0);
            a1 = fmaf(val, f.y, a1);
        }
    }
    for (; i < e; i++) {
        int   col = __ldg(&edge_col[i]);
        float val = __ldg(&edge_val[i]);
        uint32_t zz = *reinterpret_cast<const uint32_t*>(&Z[(size_t)col * F_DIM + lane * 2]);
        float2 f = __half22float2(*reinterpret_cast<__half2*>(&zz));
        a0 = fmaf(val, f.x, a0);
        a1 = fmaf(val, f.y, a1);
    }
    float m = fmaxf(a0, a1);
#pragma unroll
    for (int off = 16; off > 0; off >>= 1)
        m = fmaxf(m, __shfl_xor_sync(0xFFFFFFFFu, m, off));
    float e0 = expf(a0 - m);
    float e1 = expf(a1 - m);
    float ssum = e0 + e1;
#pragma unroll
    for (int off = 16; off > 0; off >>= 1)
        ssum += __shfl_xor_sync(0xFFFFFFFFu, ssum, off);
    float inv = 1.0f / ssum;
    *reinterpret_cast<float2*>(&out[(size_t)gw * F_DIM + lane * 2]) =
        make_float2(e0 * inv, e1 * inv);
}

// ---------------------------------------------------------------------------
// Launch
// ---------------------------------------------------------------------------
extern "C" void kernel_launch(void* const* d_in, const int* in_sizes, int n_in,
                              void* d_out, int out_size) {
    const float* X        = (const float*)d_in[0];
    const int*   edge_row = (const int*)d_in[1];
    const int*   edge_col = (const int*)d_in[2];
    const float* edge_val = (const float*)d_in[3];
    const float* W0       = (const float*)d_in[4];
    const float* Wh0      = (const float*)d_in[5];
    const float* W1       = (const float*)d_in[6];
    float*       out      = (float*)d_out;

    __half *h1, *h2, *Wh;
    cudaGetSymbolAddress((void**)&h1, g_hbuf1);
    cudaGetSymbolAddress((void**)&h2, g_hbuf2);
    cudaGetSymbolAddress((void**)&Wh, g_Wh);

    constexpr int SMEM_L0  = 3 * (128 * 160 + 128 * 80);   // 92160
    constexpr int SMEM_128 = 3 * (128 + 128) * 144;        // 110592
    constexpr int SMEM_64  = 3 * (128 + 64) * 144;         // 82944
    cudaFuncSetAttribute((const void*)gemm_l0,
                         cudaFuncAttributeMaxDynamicSharedMemorySize, SMEM_L0);
    cudaFuncSetAttribute((const void*)gemm_h<128, 128>,
                         cudaFuncAttributeMaxDynamicSharedMemorySize, SMEM_128);
    cudaFuncSetAttribute((const void*)gemm_h<64, 128>,
                         cudaFuncAttributeMaxDynamicSharedMemorySize, SMEM_64);

    const int gemm_grid = (N_NODES + 127) / 128;       // 782
    const int spmm_grid = (N_NODES * 32 + 255) / 256;  // 12500

    rowptr_kernel<<<(N_NODES + 1 + 255) / 256, 256>>>(edge_row);
    wcast_kernel<<<(14336 + 255) / 256, 256>>>(W0, Wh0, W1, Wh);

    // Layer 0: h1 = X @ W0h^T (fused fp32->fp16) ; h2 = relu(A @ h1)
    gemm_l0<<<gemm_grid, 256, SMEM_L0>>>(X, Wh, h1, N_NODES);
    spmm128_h_kernel<<<spmm_grid, 256>>>(edge_col, edge_val, h1, h2);

    // Hidden: h1 = h2 @ Wh0h^T ; h2 = relu(A @ h1)
    gemm_h<128, 128><<<gemm_grid, 256, SMEM_128>>>(h2, Wh + 32768, h1, N_NODES);
    spmm128_h_kernel<<<spmm_grid, 256>>>(edge_col, edge_val, h1, h2);

    // Output: h1 = h2 @ W1h^T ; out = softmax(A @ h1)
    gemm_h<64, 128><<<gemm_grid, 256, SMEM_64>>>(h2, Wh + 49152, h1, N_NODES);
    spmm64_softmax_kernel<<<spmm_grid, 256>>>(edge_col, edge_val, h1, out);
}